// round 2
// baseline (speedup 1.0000x reference)
#include <cuda_runtime.h>
#include <cstdint>

// Problem constants
#define BB 8
#define SS 1024
#define EE 512
#define HH 8
#define HE 4096           // H*E
#define MQ 8192           // B*S

// GEMM tiling
#define BM 128
#define BN 128
#define BK 8
#define TM 8
#define TN 8
// 256 threads per block: 16x16 thread grid, each 8x8 micro-tile

// Scratch (device globals; allocation-free per harness rules)
__device__ float g_Pq[(size_t)MQ * HE];   // 134 MB
__device__ float g_Pk[(size_t)MQ * HE];   // 134 MB
__device__ float g_Pv[(size_t)MQ * HE];   // 134 MB
__device__ float g_E [(size_t)BB * HH * SS * SS]; // 268 MB
__device__ float g_F [(size_t)MQ * HE];   // 134 MB

// ---------------------------------------------------------------------------
// C[M,N] += A[M,K] (row-major) @ B[N,K]^T (row-major, "NT")
// One 128x128 tile per block at (m0, n0). K multiple of 8; dims multiple of tile.
// ---------------------------------------------------------------------------
__device__ __forceinline__ void sgemm_tile_nt(
    const float* __restrict__ A, int lda,
    const float* __restrict__ B, int ldb,
    float* __restrict__ C, int ldc,
    int K, int m0, int n0, const float* __restrict__ bias)
{
    __shared__ float As[BK][BM];
    __shared__ float Bs[BK][BN];

    const int tid = threadIdx.x;
    const int tx  = tid & 15;
    const int ty  = tid >> 4;

    float acc[TM][TN];
#pragma unroll
    for (int i = 0; i < TM; ++i)
#pragma unroll
        for (int j = 0; j < TN; ++j) acc[i][j] = 0.0f;

    const int aRow = tid >> 1;          // 0..127
    const int aCol = (tid & 1) * 4;     // 0 or 4
    const float* Aptr = A + (size_t)(m0 + aRow) * lda + aCol;
    const float* Bptr = B + (size_t)(n0 + aRow) * ldb + aCol;

    for (int k0 = 0; k0 < K; k0 += BK) {
        float4 av = *(const float4*)(Aptr + k0);
        float4 bv = *(const float4*)(Bptr + k0);
        As[aCol + 0][aRow] = av.x;  As[aCol + 1][aRow] = av.y;
        As[aCol + 2][aRow] = av.z;  As[aCol + 3][aRow] = av.w;
        Bs[aCol + 0][aRow] = bv.x;  Bs[aCol + 1][aRow] = bv.y;
        Bs[aCol + 2][aRow] = bv.z;  Bs[aCol + 3][aRow] = bv.w;
        __syncthreads();

#pragma unroll
        for (int k = 0; k < BK; ++k) {
            float a[TM], b[TN];
            *(float4*)(a)     = *(const float4*)&As[k][ty * TM];
            *(float4*)(a + 4) = *(const float4*)&As[k][ty * TM + 4];
            *(float4*)(b)     = *(const float4*)&Bs[k][tx * TN];
            *(float4*)(b + 4) = *(const float4*)&Bs[k][tx * TN + 4];
#pragma unroll
            for (int i = 0; i < TM; ++i)
#pragma unroll
                for (int j = 0; j < TN; ++j)
                    acc[i][j] = fmaf(a[i], b[j], acc[i][j]);
        }
        __syncthreads();
    }

#pragma unroll
    for (int i = 0; i < TM; ++i) {
        float* crow = C + (size_t)(m0 + ty * TM + i) * ldc + n0 + tx * TN;
#pragma unroll
        for (int j = 0; j < TN; j += 4) {
            float4 o;
            o.x = acc[i][j + 0]; o.y = acc[i][j + 1];
            o.z = acc[i][j + 2]; o.w = acc[i][j + 3];
            if (bias) {
                const float* bp = bias + n0 + tx * TN + j;
                o.x += bp[0]; o.y += bp[1]; o.z += bp[2]; o.w += bp[3];
            }
            *(float4*)(crow + j) = o;
        }
    }
}

// ---------------------------------------------------------------------------
// C[M,N] = A[M,K] (row-major) @ B[K,N] (row-major, "NN")
// ---------------------------------------------------------------------------
__device__ __forceinline__ void sgemm_tile_nn(
    const float* __restrict__ A, int lda,
    const float* __restrict__ B, int ldb,
    float* __restrict__ C, int ldc,
    int K, int m0, int n0)
{
    __shared__ float As[BK][BM];
    __shared__ float Bs[BK][BN];

    const int tid = threadIdx.x;
    const int tx  = tid & 15;
    const int ty  = tid >> 4;

    float acc[TM][TN];
#pragma unroll
    for (int i = 0; i < TM; ++i)
#pragma unroll
        for (int j = 0; j < TN; ++j) acc[i][j] = 0.0f;

    const int aRow = tid >> 1;          // 0..127 (m)
    const int aCol = (tid & 1) * 4;     // 0 or 4 (k)
    const int bRow = tid >> 5;          // 0..7   (k)
    const int bCol = (tid & 31) * 4;    // 0..124 (n)
    const float* Aptr = A + (size_t)(m0 + aRow) * lda + aCol;
    const float* Bptr = B + (size_t)bRow * ldb + n0 + bCol;

    for (int k0 = 0; k0 < K; k0 += BK) {
        float4 av = *(const float4*)(Aptr + k0);
        float4 bv = *(const float4*)(Bptr + (size_t)k0 * ldb);
        As[aCol + 0][aRow] = av.x;  As[aCol + 1][aRow] = av.y;
        As[aCol + 2][aRow] = av.z;  As[aCol + 3][aRow] = av.w;
        *(float4*)&Bs[bRow][bCol] = bv;
        __syncthreads();

#pragma unroll
        for (int k = 0; k < BK; ++k) {
            float a[TM], b[TN];
            *(float4*)(a)     = *(const float4*)&As[k][ty * TM];
            *(float4*)(a + 4) = *(const float4*)&As[k][ty * TM + 4];
            *(float4*)(b)     = *(const float4*)&Bs[k][tx * TN];
            *(float4*)(b + 4) = *(const float4*)&Bs[k][tx * TN + 4];
#pragma unroll
            for (int i = 0; i < TM; ++i)
#pragma unroll
                for (int j = 0; j < TN; ++j)
                    acc[i][j] = fmaf(a[i], b[j], acc[i][j]);
        }
        __syncthreads();
    }

#pragma unroll
    for (int i = 0; i < TM; ++i) {
        float* crow = C + (size_t)(m0 + ty * TM + i) * ldc + n0 + tx * TN;
#pragma unroll
        for (int j = 0; j < TN; j += 4) {
            float4 o;
            o.x = acc[i][j + 0]; o.y = acc[i][j + 1];
            o.z = acc[i][j + 2]; o.w = acc[i][j + 3];
            *(float4*)(crow + j) = o;
        }
    }
}

// ---------------------------------------------------------------------------
// Kernels
// ---------------------------------------------------------------------------

// Generic NT gemm (projections + output projection)
__global__ void k_gemm_nt(const float* __restrict__ A, int lda,
                          const float* __restrict__ B, int ldb,
                          float* __restrict__ C, int ldc,
                          int K, const float* __restrict__ bias)
{
    sgemm_tile_nt(A, lda, B, ldb, C, ldc, K,
                  blockIdx.y * BM, blockIdx.x * BN, bias);
}

// Energy = Q @ K^T per (b,h); causal upper tiles skipped entirely
__global__ void k_energy(const float* __restrict__ Pq,
                         const float* __restrict__ Pk,
                         float* __restrict__ Eng)
{
    const int bh = blockIdx.z;
    const int m0 = blockIdx.y * BM;
    const int n0 = blockIdx.x * BN;
    if (n0 > m0 + BM - 1) return;   // fully masked tile
    const float* Q  = Pq + (size_t)bh * SS * EE;
    const float* Kp = Pk + (size_t)bh * SS * EE;
    float* Cc       = Eng + (size_t)bh * SS * SS;
    sgemm_tile_nt(Q, EE, Kp, EE, Cc, SS, EE, m0, n0, nullptr);
}

// Causal softmax, in-place, mask-before-scale semantics (scale = 1/8).
// One block per (row, bh). Row cached in registers: 1024/256 = 4 per thread.
__global__ void k_softmax(float* __restrict__ Eng)
{
    const int i  = blockIdx.x;       // query row
    float* row = Eng + ((size_t)blockIdx.y * SS + i) * SS;
    const int L  = i + 1;            // valid keys
    const int tid = threadIdx.x;

    float r[4];
    float lmax = -1e30f;
#pragma unroll
    for (int t = 0; t < 4; ++t) {
        int j = tid + t * 256;
        if (j < L) { r[t] = row[j]; lmax = fmaxf(lmax, r[t]); }
        else         r[t] = -1e30f;
    }

    __shared__ float red[8];
    // block max
    for (int o = 16; o; o >>= 1) lmax = fmaxf(lmax, __shfl_xor_sync(0xffffffffu, lmax, o));
    if ((tid & 31) == 0) red[tid >> 5] = lmax;
    __syncthreads();
    if (tid == 0) {
        float m = red[0];
#pragma unroll
        for (int w = 1; w < 8; ++w) m = fmaxf(m, red[w]);
        red[0] = m;
    }
    __syncthreads();
    const float m = red[0];
    __syncthreads();

    float lsum = 0.0f;
#pragma unroll
    for (int t = 0; t < 4; ++t) {
        int j = tid + t * 256;
        if (j < L) { r[t] = __expf((r[t] - m) * 0.125f); lsum += r[t]; }
        else         r[t] = 0.0f;
    }
    for (int o = 16; o; o >>= 1) lsum += __shfl_xor_sync(0xffffffffu, lsum, o);
    if ((tid & 31) == 0) red[tid >> 5] = lsum;
    __syncthreads();
    if (tid == 0) {
        float s = red[0];
#pragma unroll
        for (int w = 1; w < 8; ++w) s += red[w];
        red[0] = s;
    }
    __syncthreads();
    const float inv = 1.0f / red[0];

#pragma unroll
    for (int t = 0; t < 4; ++t) {
        int j = tid + t * 256;
        row[j] = r[t] * inv;   // zeros past the diagonal
    }
}

// F[b, s, h*E + e] = sum_j P[bh, s, j] * V[bh, j, e]  (k-loop trimmed causally)
__global__ void k_pv(const float* __restrict__ P,
                     const float* __restrict__ Pv,
                     float* __restrict__ F)
{
    const int bh = blockIdx.z;
    const int b  = bh >> 3;
    const int h  = bh & 7;
    const int m0 = blockIdx.y * BM;
    const int n0 = blockIdx.x * BN;
    const float* Pp = P  + (size_t)bh * SS * SS;
    const float* V  = Pv + (size_t)bh * SS * EE;
    float* Cc = F + (size_t)b * SS * HE + (size_t)h * EE;
    const int Klim = m0 + BM;        // keys beyond row m0+127 are all zero
    sgemm_tile_nn(Pp, SS, V, EE, Cc, HE, Klim, m0, n0);
}

// ---------------------------------------------------------------------------
extern "C" void kernel_launch(void* const* d_in, const int* in_sizes, int n_in,
                              void* d_out, int out_size)
{
    (void)in_sizes; (void)n_in; (void)out_size;
    const float* k  = (const float*)d_in[0];
    const float* v  = (const float*)d_in[1];
    const float* q  = (const float*)d_in[2];
    // d_in[3] = mask (causal tril, recomputed analytically)
    const float* Wk = (const float*)d_in[4];
    const float* Wq = (const float*)d_in[5];
    const float* Wv = (const float*)d_in[6];
    const float* Wo = (const float*)d_in[7];
    const float* bo = (const float*)d_in[8];
    float* out = (float*)d_out;

    float *Pq, *Pk, *Pv, *Em, *F;
    cudaGetSymbolAddress((void**)&Pq, g_Pq);
    cudaGetSymbolAddress((void**)&Pk, g_Pk);
    cudaGetSymbolAddress((void**)&Pv, g_Pv);
    cudaGetSymbolAddress((void**)&Em, g_E);
    cudaGetSymbolAddress((void**)&F,  g_F);

    dim3 blk(256);

    // Projections: (8192 x 512) @ (4096 x 512)^T -> (8192 x 4096)
    dim3 gp(HE / BN, MQ / BM);
    k_gemm_nt<<<gp, blk>>>(q, EE, Wq, EE, Pq, HE, EE, nullptr);
    k_gemm_nt<<<gp, blk>>>(k, EE, Wk, EE, Pk, HE, EE, nullptr);
    k_gemm_nt<<<gp, blk>>>(v, EE, Wv, EE, Pv, HE, EE, nullptr);

    // Energy: per (b,h) 1024x1024x512, causal tiles skipped
    dim3 ge(SS / BN, SS / BM, BB * HH);
    k_energy<<<ge, blk>>>(Pq, Pk, Em);

    // Softmax (mask-before-scale, in-place)
    k_softmax<<<dim3(SS, BB * HH), 256>>>(Em);

    // P @ V -> F (written pre-transposed to (B,S,H*E))
    dim3 gv(EE / BN, SS / BM, BB * HH);
    k_pv<<<gv, blk>>>(Em, Pv, F);

    // Output projection: (8192 x 4096) @ (512 x 4096)^T + bo -> (8192 x 512)
    dim3 go(EE / BN, MQ / BM);
    k_gemm_nt<<<go, blk>>>(F, HE, Wo, HE, out, EE, HE, bo);
}

// round 6
// speedup vs baseline: 2.5506x; 2.5506x over previous
#include <cuda_runtime.h>
#include <cuda_bf16.h>
#include <cstdint>

#define BB 8
#define SS 1024
#define EE 512
#define HH 8
#define HE 4096
#define MQ 8192

#define BM 128
#define BN 128
#define BKT 16

__device__ float g_Pq[(size_t)MQ * HE];
__device__ float g_Pk[(size_t)MQ * HE];
__device__ float g_Pv[(size_t)MQ * HE];
__device__ float g_E [(size_t)BB * HH * SS * SS];
__device__ float g_F [(size_t)MQ * HE];

__device__ __forceinline__ uint32_t pk2(__nv_bfloat16 a, __nv_bfloat16 b) {
    return ((uint32_t)__bfloat16_as_ushort(b) << 16) | (uint32_t)__bfloat16_as_ushort(a);
}
// split float4 (4 consecutive k) into 2 packed hi words + 2 packed lo words
__device__ __forceinline__ void split4(float4 v, uint2& hi, uint2& lo) {
    __nv_bfloat16 hx = __float2bfloat16(v.x), hy = __float2bfloat16(v.y);
    __nv_bfloat16 hz = __float2bfloat16(v.z), hw = __float2bfloat16(v.w);
    __nv_bfloat16 lx = __float2bfloat16(v.x - __bfloat162float(hx));
    __nv_bfloat16 ly = __float2bfloat16(v.y - __bfloat162float(hy));
    __nv_bfloat16 lz = __float2bfloat16(v.z - __bfloat162float(hz));
    __nv_bfloat16 lw = __float2bfloat16(v.w - __bfloat162float(hw));
    hi.x = pk2(hx, hy); hi.y = pk2(hz, hw);
    lo.x = pk2(lx, ly); lo.y = pk2(lz, lw);
}

#define MMA16(acc, a, b) \
    asm volatile("mma.sync.aligned.m16n8k16.row.col.f32.bf16.bf16.f32 " \
        "{%0,%1,%2,%3},{%4,%5,%6,%7},{%8,%9},{%0,%1,%2,%3};" \
        : "+f"((acc)[0]), "+f"((acc)[1]), "+f"((acc)[2]), "+f"((acc)[3]) \
        : "r"((a)[0]), "r"((a)[1]), "r"((a)[2]), "r"((a)[3]), \
          "r"((b)[0]), "r"((b)[1]))

// ---------------------------------------------------------------------------
// C[128,128] = A[M,K] @ op(B), bf16x3 emulated fp32 on m16n8k16 tensor cores.
// Smem planes: 128 rows x 8 u32 words (k-pairs), word swizzle w ^= (row&4).
// ---------------------------------------------------------------------------
template<bool TRANSB, bool HASBIAS>
__device__ __forceinline__ void mma_tile(
    const float* __restrict__ A, int lda,
    const float* __restrict__ B, int ldb,
    float* __restrict__ C, int ldc,
    int K, int m0, int n0, const float* __restrict__ bias)
{
    __shared__ uint32_t AsH[2][BM * 8], AsL[2][BM * 8];
    __shared__ uint32_t BsH[2][BN * 8], BsL[2][BN * 8];

    const int tid  = threadIdx.x;
    const int wid  = tid >> 5;
    const int lane = tid & 31;
    const int wm   = wid & 1;      // 2x4 warp grid; warp tile 64x32
    const int wn   = wid >> 1;
    const int qr   = lane >> 2;
    const int qc   = lane & 3;
    const int swz  = qr & 4;       // 0 or 4

    const int arow = tid >> 2;     // 0..63 (+64 second chunk)
    const int ak4  = tid & 3;      // float4 index along k16
    const int bk   = tid & 15;     // TRANSB: k within chunk
    const int bn4  = tid >> 4;     // TRANSB: n/4 (+16 second chunk)

    float acc[4][4][4];
#pragma unroll
    for (int i = 0; i < 4; ++i)
#pragma unroll
        for (int j = 0; j < 4; ++j)
#pragma unroll
            for (int r = 0; r < 4; ++r) acc[i][j][r] = 0.0f;

    float4 ar0, ar1, br0, br1;

    auto load_g = [&](int k0) {
        const float* ap = A + (size_t)(m0 + arow) * lda + k0 + ak4 * 4;
        ar0 = *(const float4*)ap;
        ar1 = *(const float4*)(ap + (size_t)64 * lda);
        if (!TRANSB) {
            const float* bp = B + (size_t)(n0 + arow) * ldb + k0 + ak4 * 4;
            br0 = *(const float4*)bp;
            br1 = *(const float4*)(bp + (size_t)64 * ldb);
        } else {
            const float* bp = B + (size_t)(k0 + bk) * ldb + n0 + bn4 * 4;
            br0 = *(const float4*)bp;
            br1 = *(const float4*)(bp + 64);
        }
    };

    auto store_s = [&](int st) {
        uint2 hi, lo;
        const int w0 = (ak4 * 2) ^ ((arow & 4) ? 4 : 0);
        const int w0b = (ak4 * 2) ^ (((arow + 64) & 4) ? 4 : 0);
        split4(ar0, hi, lo);
        *(uint2*)&AsH[st][arow * 8 + w0] = hi;
        *(uint2*)&AsL[st][arow * 8 + w0] = lo;
        split4(ar1, hi, lo);
        *(uint2*)&AsH[st][(arow + 64) * 8 + w0b] = hi;
        *(uint2*)&AsL[st][(arow + 64) * 8 + w0b] = lo;
        if (!TRANSB) {
            split4(br0, hi, lo);
            *(uint2*)&BsH[st][arow * 8 + w0] = hi;
            *(uint2*)&BsL[st][arow * 8 + w0] = lo;
            split4(br1, hi, lo);
            *(uint2*)&BsH[st][(arow + 64) * 8 + w0b] = hi;
            *(uint2*)&BsL[st][(arow + 64) * 8 + w0b] = lo;
        } else {
            // scatter-transpose: element k=bk of rows n..n+3 -> u16 halves
            const int wd = bk >> 1, hf = bk & 1;
            const float* s0 = &br0.x;
            const float* s1 = &br1.x;
#pragma unroll
            for (int j = 0; j < 4; ++j) {
                int r0 = bn4 * 4 + j, r1 = r0 + 64;
                int p0 = r0 * 8 + (wd ^ ((r0 & 4) ? 4 : 0));
                int p1 = r1 * 8 + (wd ^ ((r1 & 4) ? 4 : 0));
                __nv_bfloat16 h = __float2bfloat16(s0[j]);
                __nv_bfloat16 l = __float2bfloat16(s0[j] - __bfloat162float(h));
                ((uint16_t*)&BsH[st][p0])[hf] = __bfloat16_as_ushort(h);
                ((uint16_t*)&BsL[st][p0])[hf] = __bfloat16_as_ushort(l);
                h = __float2bfloat16(s1[j]);
                l = __float2bfloat16(s1[j] - __bfloat162float(h));
                ((uint16_t*)&BsH[st][p1])[hf] = __bfloat16_as_ushort(h);
                ((uint16_t*)&BsL[st][p1])[hf] = __bfloat16_as_ushort(l);
            }
        }
    };

    auto compute = [&](int st) {
        const int wA = qc ^ swz, wA2 = (qc + 4) ^ swz;
        uint32_t bh[4][2], bl[4][2];
#pragma unroll
        for (int nt = 0; nt < 4; ++nt) {
            int rb = (wn * 32 + nt * 8 + qr) * 8;
            bh[nt][0] = BsH[st][rb + wA];  bh[nt][1] = BsH[st][rb + wA2];
            bl[nt][0] = BsL[st][rb + wA];  bl[nt][1] = BsL[st][rb + wA2];
        }
        {
            uint32_t a[4][4];
#pragma unroll
            for (int mt = 0; mt < 4; ++mt) {
                int ra = (wm * 64 + mt * 16 + qr) * 8;
                a[mt][0] = AsH[st][ra + wA];       a[mt][1] = AsH[st][ra + 64 + wA];
                a[mt][2] = AsH[st][ra + wA2];      a[mt][3] = AsH[st][ra + 64 + wA2];
            }
#pragma unroll
            for (int mt = 0; mt < 4; ++mt)
#pragma unroll
                for (int nt = 0; nt < 4; ++nt) {
                    MMA16(acc[mt][nt], a[mt], bh[nt]);
                    MMA16(acc[mt][nt], a[mt], bl[nt]);
                }
        }
        {
            uint32_t a[4][4];
#pragma unroll
            for (int mt = 0; mt < 4; ++mt) {
                int ra = (wm * 64 + mt * 16 + qr) * 8;
                a[mt][0] = AsL[st][ra + wA];       a[mt][1] = AsL[st][ra + 64 + wA];
                a[mt][2] = AsL[st][ra + wA2];      a[mt][3] = AsL[st][ra + 64 + wA2];
            }
#pragma unroll
            for (int mt = 0; mt < 4; ++mt)
#pragma unroll
                for (int nt = 0; nt < 4; ++nt)
                    MMA16(acc[mt][nt], a[mt], bh[nt]);
        }
    };

    const int niter = K / BKT;
    load_g(0);
    store_s(0);
    __syncthreads();
    for (int kt = 1; kt < niter; ++kt) {
        load_g(kt * BKT);
        compute((kt - 1) & 1);
        store_s(kt & 1);
        __syncthreads();
    }
    compute((niter - 1) & 1);

#pragma unroll
    for (int mt = 0; mt < 4; ++mt) {
#pragma unroll
        for (int nt = 0; nt < 4; ++nt) {
            int row = m0 + wm * 64 + mt * 16 + qr;
            int col = n0 + wn * 32 + nt * 8 + qc * 2;
            float2 v0, v1;
            v0.x = acc[mt][nt][0]; v0.y = acc[mt][nt][1];
            v1.x = acc[mt][nt][2]; v1.y = acc[mt][nt][3];
            if (HASBIAS) {
                v0.x += bias[col]; v0.y += bias[col + 1];
                v1.x += bias[col]; v1.y += bias[col + 1];
            }
            *(float2*)&C[(size_t)row * ldc + col] = v0;
            *(float2*)&C[(size_t)(row + 8) * ldc + col] = v1;
        }
    }
}

// ---------------------------------------------------------------------------
__global__ void __launch_bounds__(256)
k_gemm_nt(const float* __restrict__ A, int lda,
          const float* __restrict__ B, int ldb,
          float* __restrict__ C, int ldc, int K)
{
    mma_tile<false, false>(A, lda, B, ldb, C, ldc, K,
                           blockIdx.y * BM, blockIdx.x * BN, nullptr);
}

__global__ void __launch_bounds__(256)
k_gemm_nt_bias(const float* __restrict__ A, int lda,
               const float* __restrict__ B, int ldb,
               float* __restrict__ C, int ldc, int K,
               const float* __restrict__ bias)
{
    mma_tile<false, true>(A, lda, B, ldb, C, ldc, K,
                          blockIdx.y * BM, blockIdx.x * BN, bias);
}

__global__ void __launch_bounds__(256)
k_energy(const float* __restrict__ Pq, const float* __restrict__ Pk,
         float* __restrict__ Eng)
{
    const int bh = blockIdx.z;
    const int m0 = blockIdx.y * BM;
    const int n0 = blockIdx.x * BN;
    if (n0 > m0) return;
    const float* Q  = Pq + (size_t)bh * SS * EE;
    const float* Kp = Pk + (size_t)bh * SS * EE;
    float* Cc       = Eng + (size_t)bh * SS * SS;
    mma_tile<false, false>(Q, EE, Kp, EE, Cc, SS, EE, m0, n0, nullptr);
}

__global__ void __launch_bounds__(256)
k_pv(const float* __restrict__ P, const float* __restrict__ Pv,
     float* __restrict__ F)
{
    const int bh = blockIdx.z;
    const int b  = bh >> 3;
    const int h  = bh & 7;
    const int m0 = blockIdx.y * BM;
    const int n0 = blockIdx.x * BN;
    const float* Pp = P  + (size_t)bh * SS * SS;
    const float* V  = Pv + (size_t)bh * SS * EE;
    float* Cc = F + (size_t)b * SS * HE + (size_t)h * EE;
    mma_tile<true, false>(Pp, SS, V, EE, Cc, HE, m0 + BM, m0, n0, nullptr);
}

// Causal softmax, in-place, mask-before-scale (scale = 1/8)
__global__ void k_softmax(float* __restrict__ Eng)
{
    const int i = blockIdx.x;
    float* row = Eng + ((size_t)blockIdx.y * SS + i) * SS;
    const int L = i + 1;
    const int tid = threadIdx.x;

    float r[4];
    float lmax = -1e30f;
#pragma unroll
    for (int t = 0; t < 4; ++t) {
        int j = tid + t * 256;
        if (j < L) { r[t] = row[j]; lmax = fmaxf(lmax, r[t]); }
        else         r[t] = -1e30f;
    }

    __shared__ float red[8];
    for (int o = 16; o; o >>= 1) lmax = fmaxf(lmax, __shfl_xor_sync(0xffffffffu, lmax, o));
    if ((tid & 31) == 0) red[tid >> 5] = lmax;
    __syncthreads();
    if (tid == 0) {
        float m = red[0];
#pragma unroll
        for (int w = 1; w < 8; ++w) m = fmaxf(m, red[w]);
        red[0] = m;
    }
    __syncthreads();
    const float m = red[0];
    __syncthreads();

    float lsum = 0.0f;
#pragma unroll
    for (int t = 0; t < 4; ++t) {
        int j = tid + t * 256;
        if (j < L) { r[t] = __expf((r[t] - m) * 0.125f); lsum += r[t]; }
        else         r[t] = 0.0f;
    }
    for (int o = 16; o; o >>= 1) lsum += __shfl_xor_sync(0xffffffffu, lsum, o);
    if ((tid & 31) == 0) red[tid >> 5] = lsum;
    __syncthreads();
    if (tid == 0) {
        float s = red[0];
#pragma unroll
        for (int w = 1; w < 8; ++w) s += red[w];
        red[0] = s;
    }
    __syncthreads();
    const float inv = 1.0f / red[0];

#pragma unroll
    for (int t = 0; t < 4; ++t) {
        int j = tid + t * 256;
        row[j] = r[t] * inv;
    }
}

// ---------------------------------------------------------------------------
extern "C" void kernel_launch(void* const* d_in, const int* in_sizes, int n_in,
                              void* d_out, int out_size)
{
    (void)in_sizes; (void)n_in; (void)out_size;
    const float* k  = (const float*)d_in[0];
    const float* v  = (const float*)d_in[1];
    const float* q  = (const float*)d_in[2];
    const float* Wk = (const float*)d_in[4];
    const float* Wq = (const float*)d_in[5];
    const float* Wv = (const float*)d_in[6];
    const float* Wo = (const float*)d_in[7];
    const float* bo = (const float*)d_in[8];
    float* out = (float*)d_out;

    float *Pq, *Pk, *Pv, *Em, *F;
    cudaGetSymbolAddress((void**)&Pq, g_Pq);
    cudaGetSymbolAddress((void**)&Pk, g_Pk);
    cudaGetSymbolAddress((void**)&Pv, g_Pv);
    cudaGetSymbolAddress((void**)&Em, g_E);
    cudaGetSymbolAddress((void**)&F,  g_F);

    dim3 blk(256);

    dim3 gp(HE / BN, MQ / BM);
    k_gemm_nt<<<gp, blk>>>(q, EE, Wq, EE, Pq, HE, EE);
    k_gemm_nt<<<gp, blk>>>(k, EE, Wk, EE, Pk, HE, EE);
    k_gemm_nt<<<gp, blk>>>(v, EE, Wv, EE, Pv, HE, EE);

    dim3 ge(SS / BN, SS / BM, BB * HH);
    k_energy<<<ge, blk>>>(Pq, Pk, Em);

    k_softmax<<<dim3(SS, BB * HH), 256>>>(Em);

    dim3 gv(EE / BN, SS / BM, BB * HH);
    k_pv<<<gv, blk>>>(Em, Pv, F);

    dim3 go(EE / BN, MQ / BM);
    k_gemm_nt_bias<<<go, blk>>>(F, HE, Wo, HE, out, EE, HE, bo);
}